// round 17
// baseline (speedup 1.0000x reference)
#include <cuda_runtime.h>
#include <cuda_fp16.h>
#include <cstdint>
#include <cstring>

// ---------------------------------------------------------------------------
// SyntaxGCN: GCNConv(512->256) + relu + global_mean_pool + linear(256->1) + sigmoid
// R17: R14's fp16 GEMM (mma.sync fp16 = the FLOP ceiling; fp8 mma measured
//      at the SAME FLOP rate, so reverted) + fp8(e4m3, scale 32) storage of
//      hs to halve the gather's L2 traffic (164MB -> 82MB).
//      Error: ONE ~3% fp8 source; R15 calibrated two such sources -> 3.75e-4,
//      so expect ~2e-4 final (tolerance 1e-3).
// ---------------------------------------------------------------------------

constexpr int N_NODES  = 20000;
constexpr int N_EDGES  = 320000;
constexpr int IN_DIM   = 512;
constexpr int HID      = 256;
constexpr int N_GRAPHS = 256;
constexpr int CSR_CAP  = 128;

constexpr float SH  = 32.f;                // hs scale into fp8
constexpr float RSH = 1.f / 32.f;

constexpr int TILE_M = 128;
constexpr int TILE_N = 128;
constexpr int TK     = 32;
constexpr int NCHUNK = IN_DIM / TK;        // 16
constexpr int SSTR   = 40;                 // A smem row stride (f16); LDSM conflict-free
constexpr int SSTRB  = 136;                // B smem row stride (f16); 272B -> distinct banks
constexpr int MAT    = TILE_M * SSTR;      // 5120
constexpr int OFF_B  = MAT;
constexpr int B_SZ   = TK * SSTRB;         // 4352
constexpr int STAGE  = MAT + B_SZ;         // 9472 f16
constexpr int SMEM_BYTES = 2 * STAGE * (int)sizeof(__half);  // 37888

// Scratch (device globals)
__device__ uint32_t g_hs8[N_NODES * HID / 4];    // hs fp8*SH, 4 bytes per lane
__device__ float  g_dinv[N_NODES];
__device__ int    g_cnt[N_NODES];
__device__ int    g_csr[N_NODES * CSR_CAP];
__device__ float4 g_pooled[N_GRAPHS * HID / 4];
__device__ float  g_counts[N_GRAPHS];
__device__ uint4  g_xh[N_NODES * IN_DIM / 8];    // fp16 x, pre-scaled by dinv
__device__ uint4  g_wt[IN_DIM * HID / 8];        // fp16 W, SAME layout [k][n]

// ---------------- helpers ---------------------------------------------------
__device__ __forceinline__ void red_add_v4(float4* addr, float4 v) {
    asm volatile("red.global.add.v4.f32 [%0], {%1,%2,%3,%4};"
                 :: "l"(addr), "f"(v.x), "f"(v.y), "f"(v.z), "f"(v.w)
                 : "memory");
}

__device__ __forceinline__ uint32_t smem_u32(const void* p) {
    uint32_t a;
    asm("{ .reg .u64 t; cvta.to.shared.u64 t, %1; cvt.u32.u64 %0, t; }" : "=r"(a) : "l"(p));
    return a;
}

__device__ __forceinline__ void cp16(void* dst_smem, const void* src) {
    asm volatile("cp.async.ca.shared.global [%0], [%1], 16;"
                 :: "r"(smem_u32(dst_smem)), "l"(src) : "memory");
}

__device__ __forceinline__ void ldsm_x4(uint32_t* r, uint32_t addr) {
    asm volatile("ldmatrix.sync.aligned.m8n8.x4.shared.b16 {%0,%1,%2,%3}, [%4];"
                 : "=r"(r[0]), "=r"(r[1]), "=r"(r[2]), "=r"(r[3]) : "r"(addr));
}

__device__ __forceinline__ void ldsm_x4_trans(uint32_t* r, uint32_t addr) {
    asm volatile("ldmatrix.sync.aligned.m8n8.x4.trans.shared.b16 {%0,%1,%2,%3}, [%4];"
                 : "=r"(r[0]), "=r"(r[1]), "=r"(r[2]), "=r"(r[3]) : "r"(addr));
}

__device__ __forceinline__ void mma_f16(float* c, const uint32_t* a,
                                        uint32_t b0, uint32_t b1) {
    asm volatile(
        "mma.sync.aligned.m16n8k16.row.col.f32.f16.f16.f32 "
        "{%0,%1,%2,%3}, {%4,%5,%6,%7}, {%8,%9}, {%0,%1,%2,%3};"
        : "+f"(c[0]), "+f"(c[1]), "+f"(c[2]), "+f"(c[3])
        : "r"(a[0]), "r"(a[1]), "r"(a[2]), "r"(a[3]), "r"(b0), "r"(b1));
}

__device__ __forceinline__ uint32_t f2h2(float a, float b) {
    __half2 h = __halves2half2(__float2half_rn(a), __float2half_rn(b));
    uint32_t u; memcpy(&u, &h, 4);
    return u;
}

// pack 2 floats -> 2 e4m3 bytes (low byte = lo)
__device__ __forceinline__ uint16_t f2e4m3x2(float lo, float hi) {
    uint16_t u;
    asm("cvt.rn.satfinite.e4m3x2.f32 %0, %1, %2;" : "=h"(u) : "f"(hi), "f"(lo));
    return u;
}

// --- init -------------------------------------------------------------------
__global__ void init_kernel() {
    int i = blockIdx.x * blockDim.x + threadIdx.x;
    if (i < N_GRAPHS * HID / 4) g_pooled[i] = make_float4(0.f, 0.f, 0.f, 0.f);
    if (i < N_GRAPHS)           g_counts[i] = 0.f;
    if (i < N_NODES)            g_cnt[i] = 0;
}

__global__ void edge_bin_kernel(const int* __restrict__ ei) {
    int e = blockIdx.x * blockDim.x + threadIdx.x;
    if (e >= N_EDGES) return;
    int src = __ldg(&ei[e]);
    int dst = __ldg(&ei[N_EDGES + e]);
    int pos = atomicAdd(&g_cnt[dst], 1);
    if (pos < CSR_CAP) g_csr[dst * CSR_CAP + pos] = src;
}

__global__ void dinv_kernel() {
    int n = blockIdx.x * blockDim.x + threadIdx.x;
    if (n < N_NODES) g_dinv[n] = rsqrtf((float)(g_cnt[n] + 1));
}

// --- preconvert xs = fp16(x*dinv), 4 independent float4 per thread ----------
__global__ __launch_bounds__(256) void convert_x_kernel(const float4* __restrict__ X4) {
    constexpr int TOT = N_NODES * IN_DIM / 4;       // 2,560,000 float4
    int base = blockIdx.x * 1024 + threadIdx.x;
    float4 v[4];
    int idx[4];
    #pragma unroll
    for (int q = 0; q < 4; q++) {
        idx[q] = base + 256 * q;
        if (idx[q] < TOT) v[q] = __ldg(&X4[idx[q]]);
    }
    #pragma unroll
    for (int q = 0; q < 4; q++) {
        if (idx[q] < TOT) {
            float d = __ldg(&g_dinv[idx[q] >> 7]);  // 128 float4 per row
            uint2 o;
            o.x = f2h2(v[q].x * d, v[q].y * d);
            o.y = f2h2(v[q].z * d, v[q].w * d);
            ((uint2*)g_xh)[idx[q]] = o;
        }
    }
}

// --- preconvert W -> fp16 same layout [k][n] (pure coalesced cast) ----------
__global__ __launch_bounds__(256) void convert_w_kernel(const float4* __restrict__ W4) {
    int i = blockIdx.x * blockDim.x + threadIdx.x;
    if (i >= IN_DIM * HID / 4) return;
    float4 v = W4[i];
    uint2 o;
    o.x = f2h2(v.x, v.y);
    o.y = f2h2(v.z, v.w);
    ((uint2*)g_wt)[i] = o;
}

// --- tensor-core GEMM: hs8 = fp8(SH * (xs @ W)) -----------------------------
// 256 threads, 8 warps (4m x 2n), warp tile 32x64, 2-stage cp.async.
// A: ldmatrix (row-major, [m][k] smem).  B: ldmatrix.trans ([k][n] smem).
__global__ __launch_bounds__(256, 2) void gemm_mma_kernel() {
    extern __shared__ __half sm[];
    const uint32_t smaddr = smem_u32(sm);

    const int tid  = threadIdx.x;
    const int lane = tid & 31;
    const int wid  = tid >> 5;
    const int warp_m = wid & 3;
    const int warp_n = wid >> 2;
    const int quad  = lane >> 2;
    const int tig   = lane & 3;

    const int m0 = blockIdx.y * TILE_M;
    const int n0 = blockIdx.x * TILE_N;

    const __half* xh = (const __half*)g_xh;
    const __half* wt = (const __half*)g_wt;

    float acc[2][8][4];
    #pragma unroll
    for (int i = 0; i < 2; i++)
        #pragma unroll
        for (int j = 0; j < 8; j++)
            #pragma unroll
            for (int c = 0; c < 4; c++) acc[i][j][c] = 0.f;

    // A ldmatrix lane mapping (in f16 elements)
    const int a_row = lane & 15;
    const int a_k   = (lane & 16) ? 8 : 0;
    const int a_base = (warp_m * 32 + a_row) * SSTR + a_k;
    // B ldmatrix.trans lane mapping: row = k (lane&15), col-offset = n
    const int b_k15  = lane & 15;
    const int b_noff = (lane & 16) ? 8 : 0;

    auto load_stage = [&](int s, int chunk) {
        const int k0 = chunk * TK;
        __half* st = sm + s * STAGE;
        // A: 128 rows x 32 k  (512 cp16; 2 per thread)
        #pragma unroll
        for (int r = 0; r < 2; r++) {
            int idx = tid + 256 * r;
            int row = idx >> 2;
            int c   = idx & 3;
            int gr  = m0 + row; if (gr >= N_NODES) gr = 0;
            cp16(st + row * SSTR + c * 8,
                 xh + (size_t)gr * IN_DIM + k0 + c * 8);
        }
        // B: 32 k-rows x 128 n  (512 cp16; 2 per thread), [k][n] layout
        #pragma unroll
        for (int r = 0; r < 2; r++) {
            int idx = tid + 256 * r;
            int row = idx >> 4;           // 0..31 (k)
            int c   = idx & 15;           // 16 chunks of 8 n
            cp16(st + OFF_B + row * SSTRB + c * 8,
                 wt + (size_t)(k0 + row) * HID + n0 + c * 8);
        }
    };

    load_stage(0, 0);
    asm volatile("cp.async.commit_group;" ::: "memory");

    for (int chunk = 0; chunk < NCHUNK; chunk++) {
        if (chunk + 1 < NCHUNK) load_stage((chunk + 1) & 1, chunk + 1);
        asm volatile("cp.async.commit_group;" ::: "memory");
        asm volatile("cp.async.wait_group 1;" ::: "memory");
        __syncthreads();

        const uint32_t stg = smaddr + (uint32_t)(chunk & 1) * (STAGE * 2);

        #pragma unroll
        for (int ks = 0; ks < 2; ks++) {
            const int kb = ks * 16;
            uint32_t a0[4], a1[4];
            uint32_t aa = stg + (uint32_t)(a_base + kb) * 2;
            ldsm_x4(a0, aa);
            ldsm_x4(a1, aa + 16 * SSTR * 2);
            #pragma unroll
            for (int p = 0; p < 4; p++) {
                uint32_t bh[4];
                uint32_t ba = stg + (uint32_t)(OFF_B + (kb + b_k15) * SSTRB
                                               + warp_n * 64 + p * 16 + b_noff) * 2;
                ldsm_x4_trans(bh, ba);
                mma_f16(acc[0][2 * p],     a0, bh[0], bh[1]);
                mma_f16(acc[1][2 * p],     a1, bh[0], bh[1]);
                mma_f16(acc[0][2 * p + 1], a0, bh[2], bh[3]);
                mma_f16(acc[1][2 * p + 1], a1, bh[2], bh[3]);
            }
        }
        __syncthreads();
    }

    // ---- epilogue: store hs as fp8*SH (2 bytes per acc pair) --------------
    uint16_t* hs8 = (uint16_t*)g_hs8;
    #pragma unroll
    for (int i = 0; i < 2; i++) {
        const int r0 = m0 + warp_m * 32 + i * 16 + quad;
        const int r1 = r0 + 8;
        const bool v0 = r0 < N_NODES;
        const bool v1 = r1 < N_NODES;
        #pragma unroll
        for (int j = 0; j < 8; j++) {
            const int col = n0 + warp_n * 64 + j * 8 + tig * 2;
            if (v0)
                hs8[((size_t)r0 * HID + col) >> 1] =
                    f2e4m3x2(acc[i][j][0] * SH, acc[i][j][1] * SH);
            if (v1)
                hs8[((size_t)r1 * HID + col) >> 1] =
                    f2e4m3x2(acc[i][j][2] * SH, acc[i][j][3] * SH);
        }
    }
}

// --- gather + relu + pool: one node per 64 threads, fp8 rows (256B) ---------
__global__ __launch_bounds__(256) void gather_pool_kernel(
    const int* __restrict__ batch, const float* __restrict__ b)
{
    int t = blockIdx.x * blockDim.x + threadIdx.x;
    int n = t >> 6;
    int lane = t & 63;
    if (n >= N_NODES) return;

    int cnt = g_cnt[n];
    if (cnt > CSR_CAP) cnt = CSR_CAP;
    const int* lst = g_csr + n * CSR_CAP;

    auto addrow = [&](float4& a, uint32_t raw) {
        uint32_t h0, h1;
        asm("cvt.rn.f16x2.e4m3x2 %0, %1;" : "=r"(h0) : "h"((uint16_t)(raw & 0xffff)));
        asm("cvt.rn.f16x2.e4m3x2 %0, %1;" : "=r"(h1) : "h"((uint16_t)(raw >> 16)));
        __half2 p0, p1;
        memcpy(&p0, &h0, 4);
        memcpy(&p1, &h1, 4);
        float2 f0 = __half22float2(p0);
        float2 f1 = __half22float2(p1);
        a.x += f0.x; a.y += f0.y; a.z += f1.x; a.w += f1.y;
    };

    float4 a = make_float4(0.f, 0.f, 0.f, 0.f);
    addrow(a, __ldg(&g_hs8[(size_t)n * 64 + lane]));   // self loop

    int i = 0;
    for (; i + 8 <= cnt; i += 8) {
        int s[8];
        #pragma unroll
        for (int q = 0; q < 8; q++) s[q] = __ldg(&lst[i + q]);
        uint32_t v[8];
        #pragma unroll
        for (int q = 0; q < 8; q++) v[q] = __ldg(&g_hs8[(size_t)s[q] * 64 + lane]);
        #pragma unroll
        for (int q = 0; q < 8; q++) addrow(a, v[q]);
    }
    for (; i < cnt; i++) {
        int s = __ldg(&lst[i]);
        addrow(a, __ldg(&g_hs8[(size_t)s * 64 + lane]));
    }

    float d = g_dinv[n] * RSH;             // unscale fp8 + symmetric norm
    float4 bb = __ldg((const float4*)b + lane);
    float4 v;
    v.x = fmaxf(fmaf(a.x, d, bb.x), 0.f);
    v.y = fmaxf(fmaf(a.y, d, bb.y), 0.f);
    v.z = fmaxf(fmaf(a.z, d, bb.z), 0.f);
    v.w = fmaxf(fmaf(a.w, d, bb.w), 0.f);

    int g = __ldg(&batch[n]);
    red_add_v4(&g_pooled[(size_t)g * 64 + lane], v);
    if (lane == 0) atomicAdd(&g_counts[g], 1.f);
}

// --- head --------------------------------------------------------------------
__global__ void head_kernel(
    const float* __restrict__ lin_w, const float* __restrict__ lin_b,
    float* __restrict__ out)
{
    __shared__ float red[256];
    int g = blockIdx.x;
    int t = threadIdx.x;
    const float* pooled = (const float*)g_pooled;
    red[t] = pooled[g * HID + t] * __ldg(&lin_w[t]);
    __syncthreads();
    #pragma unroll
    for (int s = 128; s > 0; s >>= 1) {
        if (t < s) red[t] += red[t + s];
        __syncthreads();
    }
    if (t == 0) {
        float cnt = fmaxf(g_counts[g], 1.f);
        float z = red[0] / cnt + __ldg(&lin_b[0]);
        out[g] = 1.f / (1.f + expf(-z));
    }
}

// ---------------------------------------------------------------------------
extern "C" void kernel_launch(void* const* d_in, const int* in_sizes, int n_in,
                              void* d_out, int out_size) {
    const float* x     = (const float*)d_in[0];
    const int*   ei    = (const int*)d_in[1];
    const int*   batch = (const int*)d_in[2];
    const float* W     = (const float*)d_in[3];
    const float* b     = (const float*)d_in[4];
    const float* lin_w = (const float*)d_in[5];
    const float* lin_b = (const float*)d_in[6];
    float*       out   = (float*)d_out;

    static bool attr_set = false;
    if (!attr_set) {
        cudaFuncSetAttribute(gemm_mma_kernel,
                             cudaFuncAttributeMaxDynamicSharedMemorySize, SMEM_BYTES);
        attr_set = true;
    }

    init_kernel<<<(N_GRAPHS * HID + 255) / 256, 256>>>();
    edge_bin_kernel<<<(N_EDGES + 255) / 256, 256>>>(ei);
    dinv_kernel<<<(N_NODES + 255) / 256, 256>>>();
    convert_x_kernel<<<(N_NODES * IN_DIM / 4 + 1023) / 1024, 256>>>((const float4*)x);
    convert_w_kernel<<<(IN_DIM * HID / 4 + 255) / 256, 256>>>((const float4*)W);
    gemm_mma_kernel<<<dim3(HID / TILE_N, (N_NODES + TILE_M - 1) / TILE_M),
                      256, SMEM_BYTES>>>();
    gather_pool_kernel<<<(N_NODES * 64 + 255) / 256, 256>>>(batch, b);
    head_kernel<<<N_GRAPHS, 256>>>(lin_w, lin_b, out);
}